// round 16
// baseline (speedup 1.0000x reference)
#include <cuda_runtime.h>
#include <cuda_bf16.h>
#include <cstdint>

#define N_NODES 50000
#define N_EDGES 600000
#define DIM 128
#define EPS 1e-5f
#define N_SBLOCKS ((N_NODES + 1023) / 1024)   // 49
#define N_TILES ((N_NODES + 127) / 128)       // 391
#define GRID_P 148

#if defined(__CUDA_ARCH__) && defined(__CUDA_ARCH_FEAT_SM103_ALL)
#define HAS_TC 1
#else
#define HAS_TC 0
#endif

// ---------------- scratch (device globals; no allocation allowed) ----------------
__device__ __align__(16) float g_s[N_NODES * DIM];    // layer-1 S
__device__ __align__(16) float g_s2[N_NODES * DIM];   // layer-2 S
__device__ int   g_cnt[N_NODES];
__device__ int   g_rowptr[N_NODES + 1];
__device__ int   g_rank[N_EDGES];
__device__ int2  g_epack[N_EDGES];
__device__ unsigned long long g_scanst[N_SBLOCKS];
// pre-swizzled W^T bf16 SMEM images (32KB each) + fused bias, per layer
__device__ __align__(16) char  g_bt_hi[2][32768];
__device__ __align__(16) char  g_bt_lo[2][32768];
__device__ __align__(16) float g_bias[2][DIM];

// blocked-atom SW128 byte offset for [128 rows x 128 bf16 cols]
__host__ __device__ __forceinline__ uint32_t sw_off(int r, int c) {
    uint32_t off = (uint32_t)((r >> 3) + (c >> 6) * 16) * 1024u + (uint32_t)(r & 7) * 128u
                 + (uint32_t)(c & 63) * 2u;
    return off ^ ((off >> 3) & 0x70);
}

// ---------------- PTX helpers (used only under HAS_TC) ----------------
__device__ __forceinline__ uint32_t smem_u32(const void* p) {
    uint32_t a;
    asm("{ .reg .u64 t; cvta.to.shared.u64 t, %1; cvt.u32.u64 %0, t; }" : "=r"(a) : "l"(p));
    return a;
}
#if HAS_TC
__device__ __forceinline__ uint32_t elect_one() {
    uint32_t p;
    asm volatile("{ .reg .pred p; elect.sync _|p, 0xFFFFFFFF; selp.b32 %0, 1, 0, p; }" : "=r"(p));
    return p;
}
#define MBAR_INIT(a, c) asm volatile("mbarrier.init.shared.b64 [%0], %1;" :: "r"(a), "r"(c) : "memory")
#define MBAR_INVAL(a)   asm volatile("mbarrier.inval.shared.b64 [%0];" :: "r"(a) : "memory")
#define MBAR_WAIT(a, ph) do {                                                              \
    uint32_t _m = (a), _p = (ph), _d;                                                      \
    asm volatile("{ .reg .pred p; mbarrier.try_wait.parity.acquire.cta.shared::cta.b64 p, [%1], %2;" \
                 " selp.b32 %0, 1, 0, p; }" : "=r"(_d) : "r"(_m), "r"(_p) : "memory");     \
    if (!_d) {                                                                             \
        asm volatile("{ .reg .pred P1; WL%=: mbarrier.try_wait.parity.acquire.cta.shared::cta.b64 P1, [%0], %1, 0x989680;" \
                     " @P1 bra.uni WD%=; bra.uni WL%=; WD%=: }" :: "r"(_m), "r"(_p) : "memory"); \
    } } while (0)
#define TC_ALLOC(sa, nc)  asm volatile("tcgen05.alloc.cta_group::1.sync.aligned.shared::cta.b32 [%0], %1;" :: "r"(sa), "r"(nc) : "memory")
#define TC_RELINQ()       asm volatile("tcgen05.relinquish_alloc_permit.cta_group::1.sync.aligned;")
#define TC_DEALLOC(t, nc) asm volatile("tcgen05.dealloc.cta_group::1.sync.aligned.b32 %0, %1;" :: "r"(t), "r"(nc))
#define TC_COMMIT(mb)     asm volatile("tcgen05.commit.cta_group::1.mbarrier::arrive::one.shared::cluster.b64 [%0];" :: "r"(mb) : "memory")
#define TC_FENCE_AFTER()  asm volatile("tcgen05.fence::after_thread_sync;" ::: "memory")
#define TC_FENCE_BEFORE() asm volatile("tcgen05.fence::before_thread_sync;" ::: "memory")
#define TC_WAIT_LD()      asm volatile("tcgen05.wait::ld.sync.aligned;" ::: "memory")

__device__ __forceinline__ void tc_mma_f16_ss(uint32_t d, uint64_t ad, uint64_t bd,
                                              uint32_t idesc, uint32_t en) {
    asm volatile("{ .reg .pred p; setp.ne.u32 p, %5, 0;"
                 " tcgen05.mma.cta_group::1.kind::f16 [%0], %1, %2, %3, {%4, %4, %4, %4}, p; }"
                 :: "r"(d), "l"(ad), "l"(bd), "r"(idesc), "r"(0u), "r"(en) : "memory");
}
#define TC_LD_X32(r, ta)                                                                   \
    asm volatile("tcgen05.ld.sync.aligned.32x32b.x32.b32 "                                 \
        "{%0,%1,%2,%3,%4,%5,%6,%7,%8,%9,%10,%11,%12,%13,%14,%15,"                          \
        "%16,%17,%18,%19,%20,%21,%22,%23,%24,%25,%26,%27,%28,%29,%30,%31}, [%32];"         \
        : "=r"((r)[0]),"=r"((r)[1]),"=r"((r)[2]),"=r"((r)[3]),"=r"((r)[4]),"=r"((r)[5]),   \
          "=r"((r)[6]),"=r"((r)[7]),"=r"((r)[8]),"=r"((r)[9]),"=r"((r)[10]),"=r"((r)[11]), \
          "=r"((r)[12]),"=r"((r)[13]),"=r"((r)[14]),"=r"((r)[15]),"=r"((r)[16]),"=r"((r)[17]),\
          "=r"((r)[18]),"=r"((r)[19]),"=r"((r)[20]),"=r"((r)[21]),"=r"((r)[22]),"=r"((r)[23]),\
          "=r"((r)[24]),"=r"((r)[25]),"=r"((r)[26]),"=r"((r)[27]),"=r"((r)[28]),"=r"((r)[29]),\
          "=r"((r)[30]),"=r"((r)[31]) : "r"(ta))

// SW128 smem descriptor (LBO=1, SBO=64, layout=2, version=1)
#define DESC_BASE ((uint64_t(2) << 61) | (uint64_t(1) << 46) | (uint64_t(64) << 32) | (uint64_t(1) << 16))
__device__ __forceinline__ uint64_t make_desc(uint32_t saddr) {
    return DESC_BASE | ((uint64_t)(saddr >> 4) & 0x3FFF);
}
// idesc: F32 accum, BF16 a/b, N=128, M=128
#define MMA_IDESC 0x8200490u
#endif  // HAS_TC

// ---------------- fused prep ----------------
__device__ __forceinline__ void prep_layer(const float* __restrict__ W,
                                           const float* __restrict__ bvec, float tval,
                                           int chunk, char* __restrict__ bhi,
                                           char* __restrict__ blo, float* __restrict__ bias,
                                           int tid_in_pair)
{
    if (chunk < 2048) {
        int n  = chunk >> 4;
        int k8 = (chunk & 15) * 8;
        uint32_t hp[4], lp[4];
        #pragma unroll
        for (int j = 0; j < 4; j++) {
            float w0 = W[(k8 + 2 * j + 1) * DIM + n];
            float w1 = W[(k8 + 2 * j + 2) * DIM + n];
            __nv_bfloat16 h0 = __float2bfloat16(w0);
            __nv_bfloat16 h1 = __float2bfloat16(w1);
            __nv_bfloat16 l0 = __float2bfloat16(w0 - __bfloat162float(h0));
            __nv_bfloat16 l1 = __float2bfloat16(w1 - __bfloat162float(h1));
            hp[j] = ((uint32_t)__bfloat16_as_ushort(h1) << 16) | __bfloat16_as_ushort(h0);
            lp[j] = ((uint32_t)__bfloat16_as_ushort(l1) << 16) | __bfloat16_as_ushort(l0);
        }
        uint32_t so = sw_off(n, k8);
        *(uint4*)(bhi + so) = make_uint4(hp[0], hp[1], hp[2], hp[3]);
        *(uint4*)(blo + so) = make_uint4(lp[0], lp[1], lp[2], lp[3]);
    }
    if (tid_in_pair < DIM)
        bias[tid_in_pair] = bvec[tid_in_pair] + tval * W[tid_in_pair];
}

__global__ __launch_bounds__(1024) void fused_prep_kernel(
    const float* __restrict__ W1, const float* __restrict__ b1,
    const float* __restrict__ W2, const float* __restrict__ b2,
    const float* __restrict__ tptr,
    char* __restrict__ bt_hi, char* __restrict__ bt_lo, float* __restrict__ bias,
    int* __restrict__ cnt, unsigned long long* __restrict__ scanst)
{
    int bid = blockIdx.x, tid = threadIdx.x;
    if (bid < 2) {
        prep_layer(W1, b1, *tptr, bid * 1024 + tid, bt_hi, bt_lo, bias,
                   (bid == 0) ? tid : 1024);
    } else if (bid < 4) {
        prep_layer(W2, b2, *tptr, (bid - 2) * 1024 + tid, bt_hi + 32768, bt_lo + 32768,
                   bias + DIM, (bid == 2) ? tid : 1024);
    } else {
        int i = (bid - 4) * 1024 + tid;
        if (i < N_NODES) cnt[i] = 0;
        if (bid == 4 && tid < N_SBLOCKS) scanst[tid] = 0ULL;
    }
}

// ---------------- CSR build ----------------
__global__ void hist_kernel(const int* __restrict__ tgt, int* __restrict__ cnt,
                            int* __restrict__ rank, int e)
{
    int i = blockIdx.x * blockDim.x + threadIdx.x;
    if (i < e) rank[i] = atomicAdd(&cnt[tgt[i]], 1);
}

__global__ __launch_bounds__(1024) void scan_kernel(
    const int* __restrict__ cnt, int* __restrict__ rowptr,
    unsigned long long* __restrict__ scanst, int n, int nb)
{
    __shared__ int wsum[32];
    __shared__ int s_prefix;
    int tid = threadIdx.x, lane = tid & 31, wid = tid >> 5;
    int bid = blockIdx.x;
    int i = bid * 1024 + tid;
    int v = (i < n) ? cnt[i] : 0;
    int x = v;
    #pragma unroll
    for (int off = 1; off < 32; off <<= 1) {
        int y = __shfl_up_sync(0xffffffffu, x, off);
        if (lane >= off) x += y;
    }
    if (lane == 31) wsum[wid] = x;
    __syncthreads();
    if (wid == 0) {
        int ws = wsum[lane];
        #pragma unroll
        for (int off = 1; off < 32; off <<= 1) {
            int y = __shfl_up_sync(0xffffffffu, ws, off);
            if (lane >= off) ws += y;
        }
        wsum[lane] = ws;
    }
    __syncthreads();
    int excl  = x - v + (wid ? wsum[wid - 1] : 0);
    int total = wsum[31];

    if (tid == 0) {
        int prefix = 0;
        if (bid == 0) {
            atomicExch(&scanst[0], (2ULL << 32) | (unsigned)total);
        } else {
            atomicExch(&scanst[bid], (1ULL << 32) | (unsigned)total);
            int j = bid - 1;
            while (true) {
                unsigned long long s = atomicAdd(&scanst[j], 0ULL);
                unsigned st = (unsigned)(s >> 32);
                if (st == 2u) { prefix += (int)(s & 0xffffffffu); break; }
                if (st == 1u) { prefix += (int)(s & 0xffffffffu); j--; }
            }
            atomicExch(&scanst[bid], (2ULL << 32) | (unsigned)(prefix + total));
        }
        s_prefix = prefix;
    }
    __syncthreads();
    if (i < n) rowptr[i] = excl + s_prefix;
    if (bid == nb - 1 && tid == 1023) rowptr[n] = s_prefix + total;
}

__global__ void scatter_kernel(const int* __restrict__ src, const int* __restrict__ tgt,
                               const float* __restrict__ ew, const int* __restrict__ rowptr,
                               const int* __restrict__ rank, int2* __restrict__ epack, int e)
{
    int i = blockIdx.x * blockDim.x + threadIdx.x;
    if (i < e) {
        int pos = rowptr[tgt[i]] + rank[i];
        epack[pos] = make_int2(src[i], __float_as_int(ew[i]));
    }
}

// ---------------- shared GEMM machinery ----------------
#define OFF_TMEM  0
#define OFF_MBAR0 8
#define OFF_MBAR1 16
#define OFF_BIAS  32
#define OFF_GN    640                       // gamma (512B) + beta (512B) for fused kernel
#define OFF_A     2048                      // 2 bufs x (hi 32KB + lo 32KB)
#define OFF_B     (2048 + 131072)
#define SMEM_TOT  (OFF_B + 65536)           // 198656 B
#define TM_D0 0
#define TM_D1 128

#if HAS_TC
__device__ __forceinline__ void drain_tile(uint32_t tmem_d, const float* __restrict__ bias_s,
                                           float* __restrict__ S, int n, int block_row,
                                           int wid, int lid)
{
    int row = block_row + (wid & 3) * 32 + lid;
    int cb = (wid >> 2) * 64;
    #pragma unroll
    for (int c = 0; c < 2; c++) {
        uint32_t r[32];
        TC_LD_X32(r, tmem_d + cb + c * 32);
        TC_WAIT_LD();
        if (row < n) {
            #pragma unroll
            for (int jj = 0; jj < 32; jj += 4) {
                float4 o;
                o.x = __uint_as_float(r[jj + 0]) + bias_s[cb + c * 32 + jj + 0];
                o.y = __uint_as_float(r[jj + 1]) + bias_s[cb + c * 32 + jj + 1];
                o.z = __uint_as_float(r[jj + 2]) + bias_s[cb + c * 32 + jj + 2];
                o.w = __uint_as_float(r[jj + 3]) + bias_s[cb + c * 32 + jj + 3];
                *(float4*)(S + (size_t)row * DIM + cb + c * 32 + jj) = o;
            }
        }
    }
}

__device__ __forceinline__ void issue_mma(uint32_t sb, uint32_t tmem, int p,
                                          const uint64_t* bB)
{
    uint64_t aB[2] = { make_desc(sb + OFF_A + p * 65536),
                       make_desc(sb + OFF_A + p * 65536 + 32768) };
    uint32_t dcol = tmem + (p ? TM_D1 : TM_D0);
    const int pa[3] = {0, 0, 1};
    const int pb[3] = {0, 1, 0};
    #pragma unroll
    for (int pp = 0; pp < 3; pp++) {
        #pragma unroll
        for (int k = 0; k < 8; k++) {
            uint64_t off = (k < 4) ? (uint64_t)(2 * k) : (uint64_t)(1024 + 2 * (k - 4));
            tc_mma_f16_ss(dcol, aB[pa[pp]] + off, bB[pb[pp]] + off, MMA_IDESC,
                          (pp != 0 || k != 0) ? 1u : 0u);
        }
    }
    TC_COMMIT(sb + OFF_MBAR0 + 8 * p);
}
#endif

// ---------------- persistent tcgen05 GEMM layer 1 (X from global) ----------------
__global__ __launch_bounds__(256, 1) void mma_gemm_kernel(
    const float* __restrict__ X, const char* __restrict__ btHi,
    const char* __restrict__ btLo, const float* __restrict__ bias,
    float* __restrict__ S, int n)
{
#if HAS_TC
    extern __shared__ char smem[];
    uint32_t sb = smem_u32(smem);
    int tid = threadIdx.x, wid = tid >> 5, lid = tid & 31;

    if (wid == 0) { TC_ALLOC(sb + OFF_TMEM, 256); TC_RELINQ(); }
    if (tid == 0) { MBAR_INIT(sb + OFF_MBAR0, 1); MBAR_INIT(sb + OFF_MBAR1, 1); }

    {
        const float4* s0 = (const float4*)btHi;
        const float4* s1 = (const float4*)btLo;
        float4* d0 = (float4*)(smem + OFF_B);
        float4* d1 = (float4*)(smem + OFF_B + 32768);
        #pragma unroll
        for (int j = 0; j < 8; j++) {
            int i = tid + j * 256;
            d0[i] = s0[i];
            d1[i] = s1[i];
        }
    }
    if (tid < DIM) ((float*)(smem + OFF_BIAS))[tid] = bias[tid];
    asm volatile("fence.proxy.async.shared::cta;" ::: "memory");
    __syncthreads();

    uint32_t tmem;
    asm volatile("ld.shared.b32 %0, [%1];" : "=r"(tmem) : "r"(sb + OFF_TMEM));
    const float* bias_s = (const float*)(smem + OFF_BIAS);
    uint64_t bB[2] = { make_desc(sb + OFF_B), make_desc(sb + OFF_B + 32768) };

    int it = 0;
    for (int tile = blockIdx.x; tile < N_TILES; tile += GRID_P, it++) {
        int p = it & 1;
        int block_row = tile * 128;

        float4 v[16];
        #pragma unroll
        for (int j = 0; j < 16; j++) {
            int i = tid + j * 256;
            int r  = i >> 5;
            int c4 = (i & 31) * 4;
            int grow = block_row + r;
            v[j] = (grow < n) ? *(const float4*)(X + (size_t)grow * DIM + c4)
                              : make_float4(0.f, 0.f, 0.f, 0.f);
        }

        if (it >= 2) {
            int j = it - 2;
            MBAR_WAIT(sb + OFF_MBAR0 + 8 * p, (j >> 1) & 1);
            TC_FENCE_AFTER();
            drain_tile(tmem + (p ? TM_D1 : TM_D0), bias_s, S, n,
                       (tile - 2 * GRID_P) * 128, wid, lid);
            TC_FENCE_BEFORE();
        }

        char* ahi = smem + OFF_A + p * 65536;
        char* alo = ahi + 32768;
        #pragma unroll
        for (int j = 0; j < 16; j++) {
            int i = tid + j * 256;
            int r  = i >> 5;
            int c4 = (i & 31) * 4;
            __nv_bfloat16 h0 = __float2bfloat16(v[j].x), h1 = __float2bfloat16(v[j].y);
            __nv_bfloat16 h2 = __float2bfloat16(v[j].z), h3 = __float2bfloat16(v[j].w);
            __nv_bfloat16 l0 = __float2bfloat16(v[j].x - __bfloat162float(h0));
            __nv_bfloat16 l1 = __float2bfloat16(v[j].y - __bfloat162float(h1));
            __nv_bfloat16 l2 = __float2bfloat16(v[j].z - __bfloat162float(h2));
            __nv_bfloat16 l3 = __float2bfloat16(v[j].w - __bfloat162float(h3));
            uint2 hv, lv;
            hv.x = ((uint32_t)__bfloat16_as_ushort(h1) << 16) | __bfloat16_as_ushort(h0);
            hv.y = ((uint32_t)__bfloat16_as_ushort(h3) << 16) | __bfloat16_as_ushort(h2);
            lv.x = ((uint32_t)__bfloat16_as_ushort(l1) << 16) | __bfloat16_as_ushort(l0);
            lv.y = ((uint32_t)__bfloat16_as_ushort(l3) << 16) | __bfloat16_as_ushort(l2);
            uint32_t so = sw_off(r, c4);
            *(uint2*)(ahi + so) = hv;
            *(uint2*)(alo + so) = lv;
        }
        asm volatile("fence.proxy.async.shared::cta;" ::: "memory");
        __syncthreads();

        if (wid == 0 && elect_one()) issue_mma(sb, tmem, p, bB);
    }

    for (int j = (it >= 2 ? it - 2 : 0); j < it; j++) {
        int m = j & 1;
        MBAR_WAIT(sb + OFF_MBAR0 + 8 * m, (j >> 1) & 1);
        TC_FENCE_AFTER();
        drain_tile(tmem + (m ? TM_D1 : TM_D0), bias_s, S, n,
                   (blockIdx.x + j * GRID_P) * 128, wid, lid);
        TC_FENCE_BEFORE();
    }

    __syncthreads();
    if (tid == 0) { MBAR_INVAL(sb + OFF_MBAR0); MBAR_INVAL(sb + OFF_MBAR1); }
    __syncthreads();
    if (wid == 0) TC_DEALLOC(tmem, 256);
#else
    int tid = threadIdx.x;
    for (int tile = blockIdx.x; tile < N_TILES; tile += GRID_P) {
        int block_row = tile * 128;
        for (int e = tid; e < 128 * DIM; e += blockDim.x) {
            int r = e >> 7, c = e & (DIM - 1);
            int grow = block_row + r;
            if (grow < n) {
                float acc = bias[c];
                for (int k = 0; k < DIM; k++) {
                    uint32_t so = sw_off(c, k);
                    float w = __bfloat162float(*(const __nv_bfloat16*)(btHi + so))
                            + __bfloat162float(*(const __nv_bfloat16*)(btLo + so));
                    acc = fmaf(X[(size_t)grow * DIM + k], w, acc);
                }
                S[(size_t)grow * DIM + c] = acc;
            }
        }
    }
#endif
}

// ---------------- agg helper: aggregate+ReLU+GN one node row, lane-local 4 cols ----
__device__ __forceinline__ float4 agg_gn_row(const float* __restrict__ S,
                                             const int* __restrict__ rowptr,
                                             const int2* __restrict__ epack,
                                             int node, int lane, float4 g, float4 b)
{
    int beg = rowptr[node];
    int end = rowptr[node + 1];
    float ax = 0.f, ay = 0.f, az = 0.f, aw = 0.f;
    int j = beg;
    for (; j + 4 <= end; j += 4) {
        int2 e0 = epack[j + 0];
        int2 e1 = epack[j + 1];
        int2 e2 = epack[j + 2];
        int2 e3 = epack[j + 3];
        float4 v0 = *(const float4*)(S + (size_t)e0.x * DIM + lane * 4);
        float4 v1 = *(const float4*)(S + (size_t)e1.x * DIM + lane * 4);
        float4 v2 = *(const float4*)(S + (size_t)e2.x * DIM + lane * 4);
        float4 v3 = *(const float4*)(S + (size_t)e3.x * DIM + lane * 4);
        float w0 = __int_as_float(e0.y), w1 = __int_as_float(e1.y);
        float w2 = __int_as_float(e2.y), w3 = __int_as_float(e3.y);
        ax = fmaf(w0, v0.x, ax); ay = fmaf(w0, v0.y, ay);
        az = fmaf(w0, v0.z, az); aw = fmaf(w0, v0.w, aw);
        ax = fmaf(w1, v1.x, ax); ay = fmaf(w1, v1.y, ay);
        az = fmaf(w1, v1.z, az); aw = fmaf(w1, v1.w, aw);
        ax = fmaf(w2, v2.x, ax); ay = fmaf(w2, v2.y, ay);
        az = fmaf(w2, v2.z, az); aw = fmaf(w2, v2.w, aw);
        ax = fmaf(w3, v3.x, ax); ay = fmaf(w3, v3.y, ay);
        az = fmaf(w3, v3.z, az); aw = fmaf(w3, v3.w, aw);
    }
    for (; j < end; j++) {
        int2 ep = epack[j];
        float w = __int_as_float(ep.y);
        float4 v = *(const float4*)(S + (size_t)ep.x * DIM + lane * 4);
        ax = fmaf(w, v.x, ax); ay = fmaf(w, v.y, ay);
        az = fmaf(w, v.z, az); aw = fmaf(w, v.w, aw);
    }
    ax = fmaxf(ax, 0.f); ay = fmaxf(ay, 0.f);
    az = fmaxf(az, 0.f); aw = fmaxf(aw, 0.f);
    float mu = (ax + ay + az + aw) * 0.25f;
    float d0 = ax - mu, d1 = ay - mu, d2 = az - mu, d3 = aw - mu;
    float var = (d0 * d0 + d1 * d1 + d2 * d2 + d3 * d3) * 0.25f;
    float inv = rsqrtf(var + EPS);
    float4 o;
    o.x = fmaf(d0 * inv, g.x, b.x);
    o.y = fmaf(d1 * inv, g.y, b.y);
    o.z = fmaf(d2 * inv, g.z, b.z);
    o.w = fmaf(d3 * inv, g.w, b.w);
    return o;
}

// ---------------- FUSED agg1 + GN + layer-2 GEMM ----------------
// Each CTA aggregates exactly the h rows of the tiles it multiplies: h never
// hits global memory. Warp w produces tile rows [16w, 16w+16).
__global__ __launch_bounds__(256, 1) void agg_mma_kernel(
    const float* __restrict__ S1, const int* __restrict__ rowptr,
    const int2* __restrict__ epack,
    const float* __restrict__ gamma, const float* __restrict__ beta,
    const char* __restrict__ btHi, const char* __restrict__ btLo,
    const float* __restrict__ bias, float* __restrict__ S2, int n)
{
#if HAS_TC
    extern __shared__ char smem[];
    uint32_t sb = smem_u32(smem);
    int tid = threadIdx.x, wid = tid >> 5, lid = tid & 31;

    if (wid == 0) { TC_ALLOC(sb + OFF_TMEM, 256); TC_RELINQ(); }
    if (tid == 0) { MBAR_INIT(sb + OFF_MBAR0, 1); MBAR_INIT(sb + OFF_MBAR1, 1); }

    {
        const float4* s0 = (const float4*)btHi;
        const float4* s1 = (const float4*)btLo;
        float4* d0 = (float4*)(smem + OFF_B);
        float4* d1 = (float4*)(smem + OFF_B + 32768);
        #pragma unroll
        for (int j = 0; j < 8; j++) {
            int i = tid + j * 256;
            d0[i] = s0[i];
            d1[i] = s1[i];
        }
    }
    if (tid < DIM) {
        ((float*)(smem + OFF_BIAS))[tid] = bias[tid];
        ((float*)(smem + OFF_GN))[tid] = gamma[tid];
        ((float*)(smem + OFF_GN + 512))[tid] = beta[tid];
    }
    asm volatile("fence.proxy.async.shared::cta;" ::: "memory");
    __syncthreads();

    uint32_t tmem;
    asm volatile("ld.shared.b32 %0, [%1];" : "=r"(tmem) : "r"(sb + OFF_TMEM));
    const float* bias_s = (const float*)(smem + OFF_BIAS);
    uint64_t bB[2] = { make_desc(sb + OFF_B), make_desc(sb + OFF_B + 32768) };
    float4 gvec = *(const float4*)((const float*)(smem + OFF_GN) + lid * 4);
    float4 bvec = *(const float4*)((const float*)(smem + OFF_GN + 512) + lid * 4);

    int it = 0;
    for (int tile = blockIdx.x; tile < N_TILES; tile += GRID_P, it++) {
        int p = it & 1;
        int block_row = tile * 128;

        // drain tile it-2 first (frees abuf[p]; MMA long done by now)
        if (it >= 2) {
            int j = it - 2;
            MBAR_WAIT(sb + OFF_MBAR0 + 8 * p, (j >> 1) & 1);
            TC_FENCE_AFTER();
            drain_tile(tmem + (p ? TM_D1 : TM_D0), bias_s, S2, n,
                       (tile - 2 * GRID_P) * 128, wid, lid);
            TC_FENCE_BEFORE();
        }

        // aggregate + GN the 16 rows this warp owns, convert to bf16, STS swizzled
        char* ahi = smem + OFF_A + p * 65536;
        char* alo = ahi + 32768;
        for (int q = 0; q < 16; q++) {
            int r = wid * 16 + q;
            int node = block_row + r;
            if (node < n) {
                float4 o = agg_gn_row(S1, rowptr, epack, node, lid, gvec, bvec);
                __nv_bfloat16 h0 = __float2bfloat16(o.x), h1 = __float2bfloat16(o.y);
                __nv_bfloat16 h2 = __float2bfloat16(o.z), h3 = __float2bfloat16(o.w);
                __nv_bfloat16 l0 = __float2bfloat16(o.x - __bfloat162float(h0));
                __nv_bfloat16 l1 = __float2bfloat16(o.y - __bfloat162float(h1));
                __nv_bfloat16 l2 = __float2bfloat16(o.z - __bfloat162float(h2));
                __nv_bfloat16 l3 = __float2bfloat16(o.w - __bfloat162float(h3));
                uint2 hv, lv;
                hv.x = ((uint32_t)__bfloat16_as_ushort(h1) << 16) | __bfloat16_as_ushort(h0);
                hv.y = ((uint32_t)__bfloat16_as_ushort(h3) << 16) | __bfloat16_as_ushort(h2);
                lv.x = ((uint32_t)__bfloat16_as_ushort(l1) << 16) | __bfloat16_as_ushort(l0);
                lv.y = ((uint32_t)__bfloat16_as_ushort(l3) << 16) | __bfloat16_as_ushort(l2);
                uint32_t so = sw_off(r, lid * 4);
                *(uint2*)(ahi + so) = hv;
                *(uint2*)(alo + so) = lv;
            } else {
                // zero pad rows beyond n so stale data can't alias (cheap, rare)
                uint32_t so = sw_off(r, lid * 4);
                *(uint2*)(ahi + so) = make_uint2(0u, 0u);
                *(uint2*)(alo + so) = make_uint2(0u, 0u);
            }
        }
        asm volatile("fence.proxy.async.shared::cta;" ::: "memory");
        __syncthreads();

        if (wid == 0 && elect_one()) issue_mma(sb, tmem, p, bB);
    }

    for (int j = (it >= 2 ? it - 2 : 0); j < it; j++) {
        int m = j & 1;
        MBAR_WAIT(sb + OFF_MBAR0 + 8 * m, (j >> 1) & 1);
        TC_FENCE_AFTER();
        drain_tile(tmem + (m ? TM_D1 : TM_D0), bias_s, S2, n,
                   (blockIdx.x + j * GRID_P) * 128, wid, lid);
        TC_FENCE_BEFORE();
    }

    __syncthreads();
    if (tid == 0) { MBAR_INVAL(sb + OFF_MBAR0); MBAR_INVAL(sb + OFF_MBAR1); }
    __syncthreads();
    if (wid == 0) TC_DEALLOC(tmem, 256);
#else
    // Fallback (never executed on GB300): h to local array per row then dot.
    int tid = threadIdx.x, wid = tid >> 5, lid = tid & 31;
    for (int tile = blockIdx.x; tile < N_TILES; tile += GRID_P) {
        int block_row = tile * 128;
        for (int q = 0; q < 16; q++) {
            int node = block_row + wid * 16 + q;
            if (node < n) {
                float4 g = *(const float4*)(gamma + lid * 4);
                float4 b = *(const float4*)(beta + lid * 4);
                float4 o = agg_gn_row(S1, rowptr, epack, node, lid, g, b);
                // write h-row to S2 temp then second pass? Simplified: direct dense dot
                // via shared broadcast is complex; use global h staging in S2 then GEMM.
                *(float4*)(S2 + (size_t)node * DIM + lid * 4) = o;
            }
        }
    }
    __syncthreads();
    // naive in-place GEMM pass (fallback only)
    for (int tile = blockIdx.x; tile < N_TILES; tile += GRID_P) {
        int block_row = tile * 128;
        for (int e = tid; e < 128 * DIM; e += 256) {
            int r = e >> 7, c = e & (DIM - 1);
            int grow = block_row + r;
            if (grow < n) {
                float acc = bias[c];
                for (int k = 0; k < DIM; k++) {
                    uint32_t so = sw_off(c, k);
                    float w = __bfloat162float(*(const __nv_bfloat16*)(btHi + so))
                            + __bfloat162float(*(const __nv_bfloat16*)(btLo + so));
                    acc = fmaf(S2[(size_t)grow * DIM + k], w, acc);
                }
                // cannot overwrite S2 while reading; fallback accuracy/perf irrelevant
                S2[(size_t)grow * DIM + c] = acc;
            }
        }
    }
#endif
}

// ---------------- standalone aggregation + ReLU + GroupNorm (layer 2 output) -----
__global__ __launch_bounds__(256) void agg_gn_kernel(
    const float* __restrict__ S, const int* __restrict__ rowptr,
    const int2* __restrict__ epack,
    const float* __restrict__ gamma, const float* __restrict__ beta,
    float* __restrict__ out, int n)
{
    int node = (blockIdx.x * blockDim.x + threadIdx.x) >> 5;
    int lane = threadIdx.x & 31;
    if (node >= n) return;
    float4 g = *(const float4*)(gamma + lane * 4);
    float4 b = *(const float4*)(beta  + lane * 4);
    float4 o = agg_gn_row(S, rowptr, epack, node, lane, g, b);
    *(float4*)(out + (size_t)node * DIM + lane * 4) = o;
}

// ---------------- launch ----------------
extern "C" void kernel_launch(void* const* d_in, const int* in_sizes, int n_in,
                              void* d_out, int out_size)
{
    const float* t      = (const float*)d_in[0];
    const float* x      = (const float*)d_in[1];
    const int*   src    = (const int*)  d_in[2];
    const int*   tgt    = (const int*)  d_in[3];
    const float* edge_w = (const float*)d_in[4];
    const float* W1     = (const float*)d_in[5];
    const float* b1     = (const float*)d_in[6];
    const float* W2     = (const float*)d_in[7];
    const float* b2     = (const float*)d_in[8];
    const float* gamma1 = (const float*)d_in[9];
    const float* beta1  = (const float*)d_in[10];
    const float* gamma2 = (const float*)d_in[11];
    const float* beta2  = (const float*)d_in[12];
    float* out = (float*)d_out;

    float* s_buf;  cudaGetSymbolAddress((void**)&s_buf,  g_s);
    float* s2_buf; cudaGetSymbolAddress((void**)&s2_buf, g_s2);
    int*   cnt;    cudaGetSymbolAddress((void**)&cnt,    g_cnt);
    int*   rowptr; cudaGetSymbolAddress((void**)&rowptr, g_rowptr);
    int*   rank;   cudaGetSymbolAddress((void**)&rank,   g_rank);
    int2*  epack;  cudaGetSymbolAddress((void**)&epack,  g_epack);
    unsigned long long* scanst; cudaGetSymbolAddress((void**)&scanst, g_scanst);
    char*  bt_hi;  cudaGetSymbolAddress((void**)&bt_hi,  g_bt_hi);
    char*  bt_lo;  cudaGetSymbolAddress((void**)&bt_lo,  g_bt_lo);
    float* bias;   cudaGetSymbolAddress((void**)&bias,   g_bias);

    cudaFuncSetAttribute(mma_gemm_kernel,
                         cudaFuncAttributeMaxDynamicSharedMemorySize, SMEM_TOT);
    cudaFuncSetAttribute(agg_mma_kernel,
                         cudaFuncAttributeMaxDynamicSharedMemorySize, SMEM_TOT);

    int agg_blocks = (N_NODES + 7) / 8;

    cudaStream_t sB;
    cudaStreamCreateWithFlags(&sB, cudaStreamNonBlocking);
    cudaEvent_t evPrep, evGemm;
    cudaEventCreateWithFlags(&evPrep, cudaEventDisableTiming);
    cudaEventCreateWithFlags(&evGemm, cudaEventDisableTiming);

    fused_prep_kernel<<<4 + N_SBLOCKS, 1024>>>(W1, b1, W2, b2, t,
                                               bt_hi, bt_lo, bias, cnt, scanst);
    cudaEventRecord(evPrep, 0);
    cudaStreamWaitEvent(sB, evPrep, 0);

    // branch B: layer-1 GEMM (depends only on prep)
    mma_gemm_kernel<<<GRID_P, 256, SMEM_TOT, sB>>>(x, bt_hi, bt_lo, bias, s_buf, N_NODES);
    cudaEventRecord(evGemm, sB);

    // branch A: CSR build (atomic-free scatter)
    hist_kernel<<<(N_EDGES + 255) / 256, 256>>>(tgt, cnt, rank, N_EDGES);
    scan_kernel<<<N_SBLOCKS, 1024>>>(cnt, rowptr, scanst, N_NODES, N_SBLOCKS);
    scatter_kernel<<<(N_EDGES + 255) / 256, 256>>>(src, tgt, edge_w, rowptr, rank,
                                                   epack, N_EDGES);

    // join: fused agg1+GN+gemm2 (h stays on-chip)
    cudaStreamWaitEvent(0, evGemm, 0);
    agg_mma_kernel<<<GRID_P, 256, SMEM_TOT>>>(s_buf, rowptr, epack, gamma1, beta1,
                                              bt_hi + 32768, bt_lo + 32768, bias + DIM,
                                              s2_buf, N_NODES);
    // layer-2 aggregation -> output
    agg_gn_kernel<<<agg_blocks, 256>>>(s2_buf, rowptr, epack, gamma2, beta2, out, N_NODES);
}

// round 17
// speedup vs baseline: 1.4921x; 1.4921x over previous
#include <cuda_runtime.h>
#include <cuda_bf16.h>
#include <cstdint>

#define N_NODES 50000
#define N_EDGES 600000
#define DIM 128
#define EPS 1e-5f
#define N_SBLOCKS ((N_NODES + 1023) / 1024)   // 49
#define N_TILES ((N_NODES + 127) / 128)       // 391
#define GRID_P 148

#if defined(__CUDA_ARCH__) && defined(__CUDA_ARCH_FEAT_SM103_ALL)
#define HAS_TC 1
#else
#define HAS_TC 0
#endif

// ---------------- scratch (device globals; no allocation allowed) ----------------
__device__ __align__(16) float g_s[N_NODES * DIM];
__device__ __align__(16) float g_h[N_NODES * DIM];
__device__ int   g_cnt[N_NODES];
__device__ int   g_rowptr[N_NODES + 1];
__device__ int   g_rank[N_EDGES];
__device__ int2  g_epack[N_EDGES];
__device__ unsigned long long g_scanst[N_SBLOCKS];   // decoupled-lookback state
// pre-swizzled W^T bf16 SMEM images (32KB each) + fused bias, per layer
__device__ __align__(16) char  g_bt_hi[2][32768];
__device__ __align__(16) char  g_bt_lo[2][32768];
__device__ __align__(16) float g_bias[2][DIM];

// blocked-atom SW128 byte offset for [128 rows x 128 bf16 cols]
__host__ __device__ __forceinline__ uint32_t sw_off(int r, int c) {
    uint32_t off = (uint32_t)((r >> 3) + (c >> 6) * 16) * 1024u + (uint32_t)(r & 7) * 128u
                 + (uint32_t)(c & 63) * 2u;
    return off ^ ((off >> 3) & 0x70);
}

// ---------------- PTX helpers (used only under HAS_TC) ----------------
__device__ __forceinline__ uint32_t smem_u32(const void* p) {
    uint32_t a;
    asm("{ .reg .u64 t; cvta.to.shared.u64 t, %1; cvt.u32.u64 %0, t; }" : "=r"(a) : "l"(p));
    return a;
}
#if HAS_TC
__device__ __forceinline__ uint32_t elect_one() {
    uint32_t p;
    asm volatile("{ .reg .pred p; elect.sync _|p, 0xFFFFFFFF; selp.b32 %0, 1, 0, p; }" : "=r"(p));
    return p;
}
#define MBAR_INIT(a, c) asm volatile("mbarrier.init.shared.b64 [%0], %1;" :: "r"(a), "r"(c) : "memory")
#define MBAR_INVAL(a)   asm volatile("mbarrier.inval.shared.b64 [%0];" :: "r"(a) : "memory")
#define MBAR_WAIT(a, ph) do {                                                              \
    uint32_t _m = (a), _p = (ph), _d;                                                      \
    asm volatile("{ .reg .pred p; mbarrier.try_wait.parity.acquire.cta.shared::cta.b64 p, [%1], %2;" \
                 " selp.b32 %0, 1, 0, p; }" : "=r"(_d) : "r"(_m), "r"(_p) : "memory");     \
    if (!_d) {                                                                             \
        asm volatile("{ .reg .pred P1; WL%=: mbarrier.try_wait.parity.acquire.cta.shared::cta.b64 P1, [%0], %1, 0x989680;" \
                     " @P1 bra.uni WD%=; bra.uni WL%=; WD%=: }" :: "r"(_m), "r"(_p) : "memory"); \
    } } while (0)
#define TC_ALLOC(sa, nc)  asm volatile("tcgen05.alloc.cta_group::1.sync.aligned.shared::cta.b32 [%0], %1;" :: "r"(sa), "r"(nc) : "memory")
#define TC_RELINQ()       asm volatile("tcgen05.relinquish_alloc_permit.cta_group::1.sync.aligned;")
#define TC_DEALLOC(t, nc) asm volatile("tcgen05.dealloc.cta_group::1.sync.aligned.b32 %0, %1;" :: "r"(t), "r"(nc))
#define TC_COMMIT(mb)     asm volatile("tcgen05.commit.cta_group::1.mbarrier::arrive::one.shared::cluster.b64 [%0];" :: "r"(mb) : "memory")
#define TC_FENCE_AFTER()  asm volatile("tcgen05.fence::after_thread_sync;" ::: "memory")
#define TC_FENCE_BEFORE() asm volatile("tcgen05.fence::before_thread_sync;" ::: "memory")
#define TC_WAIT_LD()      asm volatile("tcgen05.wait::ld.sync.aligned;" ::: "memory")

__device__ __forceinline__ void tc_mma_f16_ss(uint32_t d, uint64_t ad, uint64_t bd,
                                              uint32_t idesc, uint32_t en) {
    asm volatile("{ .reg .pred p; setp.ne.u32 p, %5, 0;"
                 " tcgen05.mma.cta_group::1.kind::f16 [%0], %1, %2, %3, {%4, %4, %4, %4}, p; }"
                 :: "r"(d), "l"(ad), "l"(bd), "r"(idesc), "r"(0u), "r"(en) : "memory");
}
#define TC_LD_X32(r, ta)                                                                   \
    asm volatile("tcgen05.ld.sync.aligned.32x32b.x32.b32 "                                 \
        "{%0,%1,%2,%3,%4,%5,%6,%7,%8,%9,%10,%11,%12,%13,%14,%15,"                          \
        "%16,%17,%18,%19,%20,%21,%22,%23,%24,%25,%26,%27,%28,%29,%30,%31}, [%32];"         \
        : "=r"((r)[0]),"=r"((r)[1]),"=r"((r)[2]),"=r"((r)[3]),"=r"((r)[4]),"=r"((r)[5]),   \
          "=r"((r)[6]),"=r"((r)[7]),"=r"((r)[8]),"=r"((r)[9]),"=r"((r)[10]),"=r"((r)[11]), \
          "=r"((r)[12]),"=r"((r)[13]),"=r"((r)[14]),"=r"((r)[15]),"=r"((r)[16]),"=r"((r)[17]),\
          "=r"((r)[18]),"=r"((r)[19]),"=r"((r)[20]),"=r"((r)[21]),"=r"((r)[22]),"=r"((r)[23]),\
          "=r"((r)[24]),"=r"((r)[25]),"=r"((r)[26]),"=r"((r)[27]),"=r"((r)[28]),"=r"((r)[29]),\
          "=r"((r)[30]),"=r"((r)[31]) : "r"(ta))

// SW128 smem descriptor (LBO=1, SBO=64, layout=2, version=1)
#define DESC_BASE ((uint64_t(2) << 61) | (uint64_t(1) << 46) | (uint64_t(64) << 32) | (uint64_t(1) << 16))
__device__ __forceinline__ uint64_t make_desc(uint32_t saddr) {
    return DESC_BASE | ((uint64_t)(saddr >> 4) & 0x3FFF);
}
// idesc: F32 accum, BF16 a/b, N=128, M=128
#define MMA_IDESC 0x8200490u
#endif  // HAS_TC

// ---------------- fused prep: W images + bias (both layers) + cnt clear + scan state ----
__device__ __forceinline__ void prep_layer(const float* __restrict__ W,
                                           const float* __restrict__ bvec, float tval,
                                           int chunk, char* __restrict__ bhi,
                                           char* __restrict__ blo, float* __restrict__ bias,
                                           int tid_in_pair)
{
    if (chunk < 2048) {
        int n  = chunk >> 4;          // row 0..127
        int k8 = (chunk & 15) * 8;    // k base, multiple of 8
        uint32_t hp[4], lp[4];
        #pragma unroll
        for (int j = 0; j < 4; j++) {
            float w0 = W[(k8 + 2 * j + 1) * DIM + n];
            float w1 = W[(k8 + 2 * j + 2) * DIM + n];
            __nv_bfloat16 h0 = __float2bfloat16(w0);
            __nv_bfloat16 h1 = __float2bfloat16(w1);
            __nv_bfloat16 l0 = __float2bfloat16(w0 - __bfloat162float(h0));
            __nv_bfloat16 l1 = __float2bfloat16(w1 - __bfloat162float(h1));
            hp[j] = ((uint32_t)__bfloat16_as_ushort(h1) << 16) | __bfloat16_as_ushort(h0);
            lp[j] = ((uint32_t)__bfloat16_as_ushort(l1) << 16) | __bfloat16_as_ushort(l0);
        }
        uint32_t so = sw_off(n, k8);
        *(uint4*)(bhi + so) = make_uint4(hp[0], hp[1], hp[2], hp[3]);
        *(uint4*)(blo + so) = make_uint4(lp[0], lp[1], lp[2], lp[3]);
    }
    if (tid_in_pair < DIM)
        bias[tid_in_pair] = bvec[tid_in_pair] + tval * W[tid_in_pair];
}

__global__ __launch_bounds__(1024) void fused_prep_kernel(
    const float* __restrict__ W1, const float* __restrict__ b1,
    const float* __restrict__ W2, const float* __restrict__ b2,
    const float* __restrict__ tptr,
    char* __restrict__ bt_hi, char* __restrict__ bt_lo, float* __restrict__ bias,
    int* __restrict__ cnt, unsigned long long* __restrict__ scanst)
{
    int bid = blockIdx.x, tid = threadIdx.x;
    if (bid < 2) {
        prep_layer(W1, b1, *tptr, bid * 1024 + tid, bt_hi, bt_lo, bias,
                   (bid == 0) ? tid : 1024);
    } else if (bid < 4) {
        prep_layer(W2, b2, *tptr, (bid - 2) * 1024 + tid, bt_hi + 32768, bt_lo + 32768,
                   bias + DIM, (bid == 2) ? tid : 1024);
    } else {
        int i = (bid - 4) * 1024 + tid;
        if (i < N_NODES) cnt[i] = 0;
        if (bid == 4 && tid < N_SBLOCKS) scanst[tid] = 0ULL;
    }
}

// ---------------- CSR build ----------------
// hist also assigns each edge its rank within its target bucket -> atomic-free scatter
__global__ void hist_kernel(const int* __restrict__ tgt, int* __restrict__ cnt,
                            int* __restrict__ rank, int e)
{
    int i = blockIdx.x * blockDim.x + threadIdx.x;
    if (i < e) rank[i] = atomicAdd(&cnt[tgt[i]], 1);
}

// single-pass decoupled-lookback scan (49 blocks, all resident -> no deadlock)
__global__ __launch_bounds__(1024) void scan_kernel(
    const int* __restrict__ cnt, int* __restrict__ rowptr,
    unsigned long long* __restrict__ scanst, int n, int nb)
{
    __shared__ int wsum[32];
    __shared__ int s_prefix;
    int tid = threadIdx.x, lane = tid & 31, wid = tid >> 5;
    int bid = blockIdx.x;
    int i = bid * 1024 + tid;
    int v = (i < n) ? cnt[i] : 0;
    int x = v;
    #pragma unroll
    for (int off = 1; off < 32; off <<= 1) {
        int y = __shfl_up_sync(0xffffffffu, x, off);
        if (lane >= off) x += y;
    }
    if (lane == 31) wsum[wid] = x;
    __syncthreads();
    if (wid == 0) {
        int ws = wsum[lane];
        #pragma unroll
        for (int off = 1; off < 32; off <<= 1) {
            int y = __shfl_up_sync(0xffffffffu, ws, off);
            if (lane >= off) ws += y;
        }
        wsum[lane] = ws;
    }
    __syncthreads();
    int excl  = x - v + (wid ? wsum[wid - 1] : 0);
    int total = wsum[31];

    if (tid == 0) {
        int prefix = 0;
        if (bid == 0) {
            atomicExch(&scanst[0], (2ULL << 32) | (unsigned)total);
        } else {
            atomicExch(&scanst[bid], (1ULL << 32) | (unsigned)total);
            int j = bid - 1;
            while (true) {
                unsigned long long s = atomicAdd(&scanst[j], 0ULL);
                unsigned st = (unsigned)(s >> 32);
                if (st == 2u) { prefix += (int)(s & 0xffffffffu); break; }
                if (st == 1u) { prefix += (int)(s & 0xffffffffu); j--; }
            }
            atomicExch(&scanst[bid], (2ULL << 32) | (unsigned)(prefix + total));
        }
        s_prefix = prefix;
    }
    __syncthreads();
    if (i < n) rowptr[i] = excl + s_prefix;
    if (bid == nb - 1 && tid == 1023) rowptr[n] = s_prefix + total;
}

// atomic-free scatter: pos = rowptr[tgt] + rank
__global__ void scatter_kernel(const int* __restrict__ src, const int* __restrict__ tgt,
                               const float* __restrict__ ew, const int* __restrict__ rowptr,
                               const int* __restrict__ rank, int2* __restrict__ epack, int e)
{
    int i = blockIdx.x * blockDim.x + threadIdx.x;
    if (i < e) {
        int pos = rowptr[tgt[i]] + rank[i];
        epack[pos] = make_int2(src[i], __float_as_int(ew[i]));
    }
}

// ---------------- persistent tcgen05 split-bf16 GEMM (SS, deep-pipelined drain) ----
// smem layout
#define OFF_TMEM  0
#define OFF_MBAR0 8
#define OFF_MBAR1 16
#define OFF_BIAS  32                        // 512B
#define OFF_A     1024                      // 2 bufs x (hi 32KB + lo 32KB)
#define OFF_B     (1024 + 131072)           // hi + lo
#define SMEM_TOT  (OFF_B + 65536)           // 197632 B
// TMEM: D ping-pong at cols 0 / 128
#define TM_D0 0
#define TM_D1 128

#if HAS_TC
// 8 warps: row-warp = wid&3 (TMEM subpartition), col half = wid>>2
__device__ __forceinline__ void drain_tile(uint32_t tmem_d, const float* __restrict__ bias_s,
                                           float* __restrict__ S, int n, int block_row,
                                           int wid, int lid)
{
    int row = block_row + (wid & 3) * 32 + lid;
    int cb = (wid >> 2) * 64;
    #pragma unroll
    for (int c = 0; c < 2; c++) {
        uint32_t r[32];
        TC_LD_X32(r, tmem_d + cb + c * 32);
        TC_WAIT_LD();
        if (row < n) {
            #pragma unroll
            for (int jj = 0; jj < 32; jj += 4) {
                float4 o;
                o.x = __uint_as_float(r[jj + 0]) + bias_s[cb + c * 32 + jj + 0];
                o.y = __uint_as_float(r[jj + 1]) + bias_s[cb + c * 32 + jj + 1];
                o.z = __uint_as_float(r[jj + 2]) + bias_s[cb + c * 32 + jj + 2];
                o.w = __uint_as_float(r[jj + 3]) + bias_s[cb + c * 32 + jj + 3];
                *(float4*)(S + (size_t)row * DIM + cb + c * 32 + jj) = o;
            }
        }
    }
}
#endif

__global__ __launch_bounds__(256, 1) void mma_gemm_kernel(
    const float* __restrict__ X, const char* __restrict__ btHi,
    const char* __restrict__ btLo, const float* __restrict__ bias,
    float* __restrict__ S, int n)
{
#if HAS_TC
    extern __shared__ char smem[];
    uint32_t sb = smem_u32(smem);
    int tid = threadIdx.x, wid = tid >> 5, lid = tid & 31;

    if (wid == 0) {
        TC_ALLOC(sb + OFF_TMEM, 256);
        TC_RELINQ();
    }
    if (tid == 0) {
        MBAR_INIT(sb + OFF_MBAR0, 1);
        MBAR_INIT(sb + OFF_MBAR1, 1);
    }

    // B images once: 2 x 2048 float4, 8/thread
    {
        const float4* s0 = (const float4*)btHi;
        const float4* s1 = (const float4*)btLo;
        float4* d0 = (float4*)(smem + OFF_B);
        float4* d1 = (float4*)(smem + OFF_B + 32768);
        #pragma unroll
        for (int j = 0; j < 8; j++) {
            int i = tid + j * 256;
            d0[i] = s0[i];
            d1[i] = s1[i];
        }
    }
    if (tid < DIM) ((float*)(smem + OFF_BIAS))[tid] = bias[tid];
    asm volatile("fence.proxy.async.shared::cta;" ::: "memory");
    __syncthreads();

    uint32_t tmem;
    asm volatile("ld.shared.b32 %0, [%1];" : "=r"(tmem) : "r"(sb + OFF_TMEM));
    const float* bias_s = (const float*)(smem + OFF_BIAS);
    uint64_t bB[2] = { make_desc(sb + OFF_B), make_desc(sb + OFF_B + 32768) };

    int it = 0;
    for (int tile = blockIdx.x; tile < N_TILES; tile += GRID_P, it++) {
        int p = it & 1;
        int block_row = tile * 128;

        // issue LDG for this tile first
        float4 v[16];
        #pragma unroll
        for (int j = 0; j < 16; j++) {
            int i = tid + j * 256;
            int r  = i >> 5;
            int c4 = (i & 31) * 4;
            int grow = block_row + r;
            v[j] = (grow < n) ? *(const float4*)(X + (size_t)grow * DIM + c4)
                              : make_float4(0.f, 0.f, 0.f, 0.f);
        }

        // deep pipeline: drain tile it-2 (same parity p) — full iteration of MMA slack;
        // also guards abuf[p] rewrite below.
        if (it >= 2) {
            int j = it - 2;
            MBAR_WAIT(sb + OFF_MBAR0 + 8 * p, (j >> 1) & 1);
            TC_FENCE_AFTER();
            drain_tile(tmem + (p ? TM_D1 : TM_D0), bias_s, S, n,
                       (tile - 2 * GRID_P) * 128, wid, lid);
            TC_FENCE_BEFORE();
        }

        // convert + swizzled STS into abuf[p] — truncation split:
        // hi = upper 16 bits of fp32 (PRMT pack), lo = x - hi (bf16x2 RN pack)
        char* ahi = smem + OFF_A + p * 65536;
        char* alo = ahi + 32768;
        #pragma unroll
        for (int j = 0; j < 16; j++) {
            int i = tid + j * 256;
            int r  = i >> 5;
            int c4 = (i & 31) * 4;
            uint32_t u0 = __float_as_uint(v[j].x), u1 = __float_as_uint(v[j].y);
            uint32_t u2 = __float_as_uint(v[j].z), u3 = __float_as_uint(v[j].w);
            uint2 hv;
            hv.x = __byte_perm(u0, u1, 0x7632);
            hv.y = __byte_perm(u2, u3, 0x7632);
            float l0 = v[j].x - __uint_as_float(u0 & 0xFFFF0000u);
            float l1 = v[j].y - __uint_as_float(u1 & 0xFFFF0000u);
            float l2 = v[j].z - __uint_as_float(u2 & 0xFFFF0000u);
            float l3 = v[j].w - __uint_as_float(u3 & 0xFFFF0000u);
            __nv_bfloat162 p0 = __floats2bfloat162_rn(l0, l1);
            __nv_bfloat162 p1 = __floats2bfloat162_rn(l2, l3);
            uint2 lv;
            lv.x = *(uint32_t*)&p0;
            lv.y = *(uint32_t*)&p1;
            uint32_t so = sw_off(r, c4);
            *(uint2*)(ahi + so) = hv;
            *(uint2*)(alo + so) = lv;
        }
        asm volatile("fence.proxy.async.shared::cta;" ::: "memory");
        __syncthreads();

        if (wid == 0 && elect_one()) {
            uint64_t aB[2] = { make_desc(sb + OFF_A + p * 65536),
                               make_desc(sb + OFF_A + p * 65536 + 32768) };
            uint32_t dcol = tmem + (p ? TM_D1 : TM_D0);
            const int pa[3] = {0, 0, 1};
            const int pb[3] = {0, 1, 0};
            #pragma unroll
            for (int pp = 0; pp < 3; pp++) {
                #pragma unroll
                for (int k = 0; k < 8; k++) {
                    uint64_t off = (k < 4) ? (uint64_t)(2 * k) : (uint64_t)(1024 + 2 * (k - 4));
                    tc_mma_f16_ss(dcol, aB[pa[pp]] + off, bB[pb[pp]] + off, MMA_IDESC,
                                  (pp != 0 || k != 0) ? 1u : 0u);
                }
            }
            TC_COMMIT(sb + OFF_MBAR0 + 8 * p);
        }
    }

    // tail drains: last two tiles
    for (int j = (it >= 2 ? it - 2 : 0); j < it; j++) {
        int m = j & 1;
        MBAR_WAIT(sb + OFF_MBAR0 + 8 * m, (j >> 1) & 1);
        TC_FENCE_AFTER();
        drain_tile(tmem + (m ? TM_D1 : TM_D0), bias_s, S, n,
                   (blockIdx.x + j * GRID_P) * 128, wid, lid);
        TC_FENCE_BEFORE();
    }

    __syncthreads();
    if (tid == 0) {
        MBAR_INVAL(sb + OFF_MBAR0);
        MBAR_INVAL(sb + OFF_MBAR1);
    }
    __syncthreads();
    if (wid == 0) TC_DEALLOC(tmem, 256);
#else
    // Functional fallback for the compatibility-PTX pass. Never executed on GB300.
    int tid = threadIdx.x;
    for (int tile = blockIdx.x; tile < N_TILES; tile += GRID_P) {
        int block_row = tile * 128;
        for (int e = tid; e < 128 * DIM; e += blockDim.x) {
            int r = e >> 7, c = e & (DIM - 1);
            int grow = block_row + r;
            if (grow < n) {
                float acc = bias[c];
                for (int k = 0; k < DIM; k++) {
                    uint32_t so = sw_off(c, k);
                    float w = __bfloat162float(*(const __nv_bfloat16*)(btHi + so))
                            + __bfloat162float(*(const __nv_bfloat16*)(btLo + so));
                    acc = fmaf(X[(size_t)grow * DIM + k], w, acc);
                }
                S[(size_t)grow * DIM + c] = acc;
            }
        }
    }
#endif
}

// ---------------- aggregation + ReLU + GroupNorm (group size 4 == one lane) ----------------
__global__ __launch_bounds__(256) void agg_gn_kernel(
    const float* __restrict__ S, const int* __restrict__ rowptr,
    const int2* __restrict__ epack,
    const float* __restrict__ gamma, const float* __restrict__ beta,
    float* __restrict__ out, int n)
{
    int warp = (blockIdx.x * blockDim.x + threadIdx.x) >> 5;
    int lane = threadIdx.x & 31;
    if (warp >= n) return;

    int beg = rowptr[warp];
    int end = rowptr[warp + 1];

    float ax = 0.f, ay = 0.f, az = 0.f, aw = 0.f;
    int j = beg;
    for (; j + 4 <= end; j += 4) {
        int2 e0 = epack[j + 0];
        int2 e1 = epack[j + 1];
        int2 e2 = epack[j + 2];
        int2 e3 = epack[j + 3];
        float4 v0 = *(const float4*)(S + (size_t)e0.x * DIM + lane * 4);
        float4 v1 = *(const float4*)(S + (size_t)e1.x * DIM + lane * 4);
        float4 v2 = *(const float4*)(S + (size_t)e2.x * DIM + lane * 4);
        float4 v3 = *(const float4*)(S + (size_t)e3.x * DIM + lane * 4);
        float w0 = __int_as_float(e0.y), w1 = __int_as_float(e1.y);
        float w2 = __int_as_float(e2.y), w3 = __int_as_float(e3.y);
        ax = fmaf(w0, v0.x, ax); ay = fmaf(w0, v0.y, ay);
        az = fmaf(w0, v0.z, az); aw = fmaf(w0, v0.w, aw);
        ax = fmaf(w1, v1.x, ax); ay = fmaf(w1, v1.y, ay);
        az = fmaf(w1, v1.z, az); aw = fmaf(w1, v1.w, aw);
        ax = fmaf(w2, v2.x, ax); ay = fmaf(w2, v2.y, ay);
        az = fmaf(w2, v2.z, az); aw = fmaf(w2, v2.w, aw);
        ax = fmaf(w3, v3.x, ax); ay = fmaf(w3, v3.y, ay);
        az = fmaf(w3, v3.z, az); aw = fmaf(w3, v3.w, aw);
    }
    for (; j < end; j++) {
        int2 ep = epack[j];
        float w = __int_as_float(ep.y);
        float4 v = *(const float4*)(S + (size_t)ep.x * DIM + lane * 4);
        ax = fmaf(w, v.x, ax); ay = fmaf(w, v.y, ay);
        az = fmaf(w, v.z, az); aw = fmaf(w, v.w, aw);
    }
    ax = fmaxf(ax, 0.f); ay = fmaxf(ay, 0.f);
    az = fmaxf(az, 0.f); aw = fmaxf(aw, 0.f);
    float mu = (ax + ay + az + aw) * 0.25f;
    float d0 = ax - mu, d1 = ay - mu, d2 = az - mu, d3 = aw - mu;
    float var = (d0 * d0 + d1 * d1 + d2 * d2 + d3 * d3) * 0.25f;
    float inv = rsqrtf(var + EPS);
    float4 g = *(const float4*)(gamma + lane * 4);
    float4 b = *(const float4*)(beta  + lane * 4);
    float4 o;
    o.x = fmaf(d0 * inv, g.x, b.x);
    o.y = fmaf(d1 * inv, g.y, b.y);
    o.z = fmaf(d2 * inv, g.z, b.z);
    o.w = fmaf(d3 * inv, g.w, b.w);
    *(float4*)(out + (size_t)warp * DIM + lane * 4) = o;
}

// ---------------- launch ----------------
extern "C" void kernel_launch(void* const* d_in, const int* in_sizes, int n_in,
                              void* d_out, int out_size)
{
    const float* t      = (const float*)d_in[0];
    const float* x      = (const float*)d_in[1];
    const int*   src    = (const int*)  d_in[2];
    const int*   tgt    = (const int*)  d_in[3];
    const float* edge_w = (const float*)d_in[4];
    const float* W1     = (const float*)d_in[5];
    const float* b1     = (const float*)d_in[6];
    const float* W2     = (const float*)d_in[7];
    const float* b2     = (const float*)d_in[8];
    const float* gamma1 = (const float*)d_in[9];
    const float* beta1  = (const float*)d_in[10];
    const float* gamma2 = (const float*)d_in[11];
    const float* beta2  = (const float*)d_in[12];
    float* out = (float*)d_out;

    float* s_buf;  cudaGetSymbolAddress((void**)&s_buf,  g_s);
    float* h_buf;  cudaGetSymbolAddress((void**)&h_buf,  g_h);
    int*   cnt;    cudaGetSymbolAddress((void**)&cnt,    g_cnt);
    int*   rowptr; cudaGetSymbolAddress((void**)&rowptr, g_rowptr);
    int*   rank;   cudaGetSymbolAddress((void**)&rank,   g_rank);
    int2*  epack;  cudaGetSymbolAddress((void**)&epack,  g_epack);
    unsigned long long* scanst; cudaGetSymbolAddress((void**)&scanst, g_scanst);
    char*  bt_hi;  cudaGetSymbolAddress((void**)&bt_hi,  g_bt_hi);
    char*  bt_lo;  cudaGetSymbolAddress((void**)&bt_lo,  g_bt_lo);
    float* bias;   cudaGetSymbolAddress((void**)&bias,   g_bias);

    cudaFuncSetAttribute(mma_gemm_kernel,
                         cudaFuncAttributeMaxDynamicSharedMemorySize, SMEM_TOT);

    int agg_blocks = (N_NODES + 7) / 8;

    // Fork a side stream so gemm1 (branch B) runs concurrently with the CSR build
    // (branch A: hist -> scan -> scatter, atomic-free). Events become graph edges.
    cudaStream_t sB;
    cudaStreamCreateWithFlags(&sB, cudaStreamNonBlocking);
    cudaEvent_t evPrep, evGemm;
    cudaEventCreateWithFlags(&evPrep, cudaEventDisableTiming);
    cudaEventCreateWithFlags(&evGemm, cudaEventDisableTiming);

    fused_prep_kernel<<<4 + N_SBLOCKS, 1024>>>(W1, b1, W2, b2, t,
                                               bt_hi, bt_lo, bias, cnt, scanst);
    cudaEventRecord(evPrep, 0);
    cudaStreamWaitEvent(sB, evPrep, 0);

    // branch B: layer-1 GEMM (depends only on prep)
    mma_gemm_kernel<<<GRID_P, 256, SMEM_TOT, sB>>>(x, bt_hi, bt_lo, bias, s_buf, N_NODES);
    cudaEventRecord(evGemm, sB);

    // branch A: CSR build (atomic-free scatter)
    hist_kernel<<<(N_EDGES + 255) / 256, 256>>>(tgt, cnt, rank, N_EDGES);
    scan_kernel<<<N_SBLOCKS, 1024>>>(cnt, rowptr, scanst, N_NODES, N_SBLOCKS);
    scatter_kernel<<<(N_EDGES + 255) / 256, 256>>>(src, tgt, edge_w, rowptr, rank,
                                                   epack, N_EDGES);

    // join: agg1 needs both branches
    cudaStreamWaitEvent(0, evGemm, 0);
    agg_gn_kernel<<<agg_blocks, 256>>>(s_buf, rowptr, epack, gamma1, beta1, h_buf, N_NODES);
    mma_gemm_kernel<<<GRID_P, 256, SMEM_TOT>>>(h_buf, bt_hi + 32768, bt_lo + 32768,
                                               bias + DIM, s_buf, N_NODES);
    agg_gn_kernel<<<agg_blocks, 256>>>(s_buf, rowptr, epack, gamma2, beta2, out, N_NODES);
}